// round 1
// baseline (speedup 1.0000x reference)
#include <cuda_runtime.h>
#include <cstdint>

// Problem constants
#define Nn 32
#define Cc 64
#define HW 16384            // 128*128
#define CHW (Cc*HW)         // 1048576
#define NCOLS_S 58255       // number of subsampled columns (524288 cols, stride 9)
#define NCHUNK 911          // ceil(58255/64)
#define EPSF 0.01f
#define GRID_GRAM 256
#define GRID_APPLY 2048     // 32 n * 64 p-tiles of 256

typedef unsigned long long ull;

// ---------------- f32x2 helpers (Blackwell FFMA2) ----------------
__device__ __forceinline__ ull pack2(float x, float y) {
    ull r; asm("mov.b64 %0, {%1,%2};" : "=l"(r) : "f"(x), "f"(y)); return r;
}
__device__ __forceinline__ void unpack2(ull v, float& x, float& y) {
    asm("mov.b64 {%0,%1}, %2;" : "=f"(x), "=f"(y) : "l"(v));
}
__device__ __forceinline__ void ffma2(ull& d, ull a, ull b) {
    asm("fma.rn.f32x2 %0, %1, %2, %3;" : "=l"(d) : "l"(a), "l"(b), "l"(d));
}

// ---------------- device scratch (no allocation allowed) ----------------
__device__ float g_part[GRID_GRAM * 4096];   // per-block Gram partials (4 MB)
__device__ float g_rspart[GRID_GRAM * 64];   // per-block rowsum partials
__device__ float g_gram[4096];
__device__ float g_rowsum[64];
__device__ ull   g_deconv2[4096];            // deconv[c][b] duplicated as {d,d}
__device__ float g_dmean[64];

// =====================================================================
// Pass 1: Gram of subsampled columns + row sums (deterministic partials)
// =====================================================================
__global__ void __launch_bounds__(256) gram_kernel(const float* __restrict__ x) {
    __shared__ float asub[64][64];   // [scol][b]
    __shared__ float ps[256];

    const int t = threadIdx.x;
    const int bid = blockIdx.x;
    const int b = t & 63;
    const int g = t >> 6;
    const int ti = t >> 4, tj = t & 15;
    const int i0 = ti * 4, j0 = tj * 4;

    float acc[4][4];
#pragma unroll
    for (int p = 0; p < 4; p++)
#pragma unroll
        for (int q = 0; q < 4; q++) acc[p][q] = 0.f;
    float rs = 0.f;

    for (int chunk = bid; chunk < NCHUNK; chunk += GRID_GRAM) {
        float vals[16];
#pragma unroll
        for (int k = 0; k < 16; k++) {
            const int scol = g * 16 + k;
            const int s = chunk * 64 + scol;
            float v = 0.f;
            if (s < NCOLS_S) {
                const int col = s * 9;
                const int n = col >> 14;
                const int p = col & 16383;
                v = x[n * CHW + b * HW + p];
            }
            vals[k] = v;
            rs += v;
        }
        __syncthreads();   // previous chunk's compute done before overwrite
#pragma unroll
        for (int k = 0; k < 16; k++) asub[g * 16 + k][b] = vals[k];
        __syncthreads();

#pragma unroll 4
        for (int scol = 0; scol < 64; scol++) {
            const float4 av = *(const float4*)&asub[scol][i0];
            const float4 bv = *(const float4*)&asub[scol][j0];
            const float ar[4] = {av.x, av.y, av.z, av.w};
            const float br[4] = {bv.x, bv.y, bv.z, bv.w};
#pragma unroll
            for (int p = 0; p < 4; p++)
#pragma unroll
                for (int q = 0; q < 4; q++)
                    acc[p][q] = fmaf(ar[p], br[q], acc[p][q]);
        }
    }

    float* gp = &g_part[bid * 4096];
#pragma unroll
    for (int p = 0; p < 4; p++)
#pragma unroll
        for (int q = 0; q < 4; q++)
            gp[(i0 + p) * 64 + (j0 + q)] = acc[p][q];

    __syncthreads();
    ps[t] = rs;
    __syncthreads();
    if (t < 64)
        g_rspart[bid * 64 + t] = ps[t] + ps[t + 64] + ps[t + 128] + ps[t + 192];
}

// =====================================================================
// Deterministic reduction of partials
// =====================================================================
__global__ void __launch_bounds__(256) reduce_kernel() {
    const int idx = blockIdx.x * 256 + threadIdx.x;  // 16 blocks -> 4096
    float s = 0.f;
    for (int k = 0; k < GRID_GRAM; k++) s += g_part[k * 4096 + idx];
    g_gram[idx] = s;
    if (blockIdx.x == 0 && threadIdx.x < 64) {
        float r = 0.f;
        for (int k = 0; k < GRID_GRAM; k++) r += g_rspart[k * 64 + threadIdx.x];
        g_rowsum[threadIdx.x] = r;
    }
}

// =====================================================================
// Newton-Schulz inverse sqrt (single block) -> g_deconv2, g_dmean
// =====================================================================
__device__ __forceinline__ void mm64(float* __restrict__ D,
                                     const float* __restrict__ A,
                                     const float* __restrict__ B,
                                     int t, bool thalf) {
    const int i0 = (t >> 4) * 4, j0 = (t & 15) * 4;
    ull acc[4][2];
#pragma unroll
    for (int a = 0; a < 4; a++) { acc[a][0] = 0ull; acc[a][1] = 0ull; }

#pragma unroll 8
    for (int b = 0; b < 64; b++) {
        const ulonglong2 bv = *(const ulonglong2*)(B + b * 64 + j0);
#pragma unroll
        for (int a = 0; a < 4; a++) {
            const float av = A[(i0 + a) * 64 + b];
            const ull ad = pack2(av, av);
            ffma2(acc[a][0], ad, bv.x);
            ffma2(acc[a][1], ad, bv.y);
        }
    }
#pragma unroll
    for (int a = 0; a < 4; a++) {
        const int i = i0 + a;
#pragma unroll
        for (int h = 0; h < 2; h++) {
            float vx, vy; unpack2(acc[a][h], vx, vy);
            const int j = j0 + h * 2;
            if (thalf) {
                vx = (i == j     ? 1.5f : 0.f) - 0.5f * vx;
                vy = (i == j + 1 ? 1.5f : 0.f) - 0.5f * vy;
            }
            D[i * 64 + j]     = vx;
            D[i * 64 + j + 1] = vy;
        }
    }
}

#define NS_SMEM ((4 * 4096 + 256) * 4)

__global__ void __launch_bounds__(256) ns_kernel() {
    extern __shared__ float sm[];
    float* M0 = sm;
    float* M1 = sm + 4096;
    float* M2 = sm + 8192;
    float* M3 = sm + 12288;
    float* red = sm + 16384;

    const int t = threadIdx.x;
    const int i0 = (t >> 4) * 4, j0 = (t & 15) * 4;
    const float invn = 1.0f / (float)NCOLS_S;

    // cov = gram/ncols + eps*I into M0, accumulate Frobenius^2
    float ss = 0.f;
#pragma unroll
    for (int a = 0; a < 4; a++)
#pragma unroll
        for (int c = 0; c < 4; c++) {
            const int i = i0 + a, j = j0 + c;
            float v = g_gram[i * 64 + j] * invn + ((i == j) ? EPSF : 0.f);
            M0[i * 64 + j] = v;
            ss += v * v;
        }
    red[t] = ss;
    __syncthreads();
    for (int off = 128; off > 0; off >>= 1) {
        if (t < off) red[t] += red[t + off];
        __syncthreads();
    }
    const float normA = sqrtf(red[0]);
    const float inv = 1.0f / normA;

    // Y = cov/normA (M1), Z = I (M2)
#pragma unroll
    for (int a = 0; a < 4; a++)
#pragma unroll
        for (int c = 0; c < 4; c++) {
            const int i = i0 + a, j = j0 + c;
            M1[i * 64 + j] = M0[i * 64 + j] * inv;
            M2[i * 64 + j] = (i == j) ? 1.f : 0.f;
        }
    __syncthreads();

    float *Y = M1, *Z = M2, *T = M0, *U = M3;
    for (int it = 0; it < 5; it++) {
        mm64(T, Z, Y, t, true);   __syncthreads();   // T = 1.5I - 0.5 Z@Y
        mm64(U, Y, T, t, false);  __syncthreads();   // U = Y@T (new Y)
        mm64(Y, T, Z, t, false);  __syncthreads();   // old-Y slot = T@Z (new Z)
        float* oldY = Y; float* oldZ = Z;
        Y = U; Z = oldY; U = oldZ;
    }

    const float sc = 1.0f / sqrtf(normA);
#pragma unroll
    for (int a = 0; a < 4; a++)
#pragma unroll
        for (int c = 0; c < 4; c++) {
            const int i = i0 + a, j = j0 + c;
            const float d = Z[i * 64 + j] * sc;
            g_deconv2[i * 64 + j] = pack2(d, d);
        }
    __syncthreads();
    if (t < 64) {
        float dm = 0.f;
        for (int b = 0; b < 64; b++)
            dm += Z[t * 64 + b] * sc * (g_rowsum[b] * invn);
        g_dmean[t] = dm;
    }
}

// =====================================================================
// Pass 2: y = deconv @ x - dmean  (FFMA2-tiled, smem-staged)
// =====================================================================
#define APPLY_SMEM (64 * 256 * 4 + 4096 * 8 + 64 * 4)

__global__ void __launch_bounds__(256, 2) apply_kernel(const float* __restrict__ x,
                                                       float* __restrict__ y) {
    extern __shared__ float smem[];
    float* xs = smem;                       // [64][256]
    ull*   dsp = (ull*)(smem + 16384);      // [64][64] packed {d,d}
    float* dm  = smem + 16384 + 8192;       // [64]

    const int t = threadIdx.x;
    const int bid = blockIdx.x;
    const int n = bid >> 6;
    const int p0 = (bid & 63) << 8;

    // stage deconv + dmean
#pragma unroll
    for (int k = 0; k < 16; k++) dsp[k * 256 + t] = g_deconv2[k * 256 + t];
    if (t < 64) dm[t] = g_dmean[t];

    // stage x tile [64 channels][256 cols]
    const float* xb = x + n * CHW + p0;
#pragma unroll
    for (int k = 0; k < 16; k++) {
        const int v = k * 256 + t;
        const int row = v >> 6;
        const int cv = (v & 63) << 2;
        *(float4*)&xs[row * 256 + cv] = *(const float4*)&xb[row * HW + cv];
    }
    __syncthreads();

    const int cg = t >> 6;          // 0..3 -> 16 output channels each
    const int q  = t & 63;
    const int j0 = q << 2;          // 4 columns (2 f32x2)
    const int c0 = cg << 4;

    ull acc[16][2];
#pragma unroll
    for (int c = 0; c < 16; c++) { acc[c][0] = 0ull; acc[c][1] = 0ull; }

#pragma unroll 8
    for (int b = 0; b < 64; b++) {
        const ulonglong2 xv = *(const ulonglong2*)&xs[b * 256 + j0];
#pragma unroll
        for (int c = 0; c < 16; c++) {
            const ull d = dsp[(c0 + c) * 64 + b];
            ffma2(acc[c][0], d, xv.x);
            ffma2(acc[c][1], d, xv.y);
        }
    }

    float* yb = y + n * CHW + p0;
#pragma unroll
    for (int c = 0; c < 16; c++) {
        const float dmv = dm[c0 + c];
        float a0x, a0y, a1x, a1y;
        unpack2(acc[c][0], a0x, a0y);
        unpack2(acc[c][1], a1x, a1y);
        float4 o;
        o.x = a0x - dmv; o.y = a0y - dmv; o.z = a1x - dmv; o.w = a1y - dmv;
        *(float4*)&yb[(c0 + c) * HW + j0] = o;
    }
}

// =====================================================================
extern "C" void kernel_launch(void* const* d_in, const int* in_sizes, int n_in,
                              void* d_out, int out_size) {
    (void)in_sizes; (void)n_in; (void)out_size;
    const float* x = (const float*)d_in[0];
    float* y = (float*)d_out;

    cudaFuncSetAttribute(ns_kernel, cudaFuncAttributeMaxDynamicSharedMemorySize, NS_SMEM);
    cudaFuncSetAttribute(apply_kernel, cudaFuncAttributeMaxDynamicSharedMemorySize, APPLY_SMEM);

    gram_kernel<<<GRID_GRAM, 256>>>(x);
    reduce_kernel<<<16, 256>>>();
    ns_kernel<<<1, 256, NS_SMEM>>>();
    apply_kernel<<<GRID_APPLY, 256, APPLY_SMEM>>>(x, y);
}